// round 12
// baseline (speedup 1.0000x reference)
#include <cuda_runtime.h>
#include <math.h>

#define BB   4
#define CIN  64
#define C2   340
#define HID  170
#define HH   256
#define WW   256
#define NPIX 65536   /* 256*256 */

// ---------------- scratch (device globals; no allocations) ----------------
__device__ float g_xd[BB * CIN * NPIX];          // DCT(x): 67 MB
__device__ float g_yq[BB * C2  * NPIX];          // quant * (W_in @ DCT(x)): 356 MB
__device__ float g_g [BB * HID * NPIX];          // gelu(x1)*x2: 178 MB
__device__ float g_Wt [64  * 384];               // W_in^T  [k][m], stride 384 (zero padded)
__device__ float g_Wot[192 * 64];                // W_out^T [k][m], K padded 170->192

__device__ __forceinline__ unsigned f2tf(float f) {
    unsigned u;
    asm("cvt.rna.tf32.f32 %0, %1;" : "=r"(u) : "f"(f));
    return u;
}
// split x into tf32 hi + tf32 lo (x ~= hi + lo to ~2^-22 rel)
__device__ __forceinline__ void tfsplit(float x, unsigned& hi, unsigned& lo) {
    hi = f2tf(x);
    lo = f2tf(x - __uint_as_float(hi));
}

#define MMA_TF32(C, A0, A1, A2, A3, B0, B1)                                  \
    asm("mma.sync.aligned.m16n8k8.row.col.f32.tf32.tf32.f32 "                \
        "{%0,%1,%2,%3}, {%4,%5,%6,%7}, {%8,%9}, {%0,%1,%2,%3};"              \
        : "+f"(C[0]), "+f"(C[1]), "+f"(C[2]), "+f"(C[3])                     \
        : "r"(A0), "r"(A1), "r"(A2), "r"(A3), "r"(B0), "r"(B1))

// ---------------- tiny transpose of the weight matrices ----------------
__global__ void k_transpose(const float* __restrict__ W_in,
                            const float* __restrict__ W_out) {
    int t = blockIdx.x * blockDim.x + threadIdx.x;
    if (t < C2 * CIN) {               // W_in [340][64] -> g_Wt [64][384]
        int m = t / CIN, k = t % CIN;
        g_Wt[k * 384 + m] = W_in[t];
    }
    if (t < 64 * HID) {               // W_out [64][170] -> g_Wot [170][64]
        int m = t / HID, k = t % HID;
        g_Wot[k * 64 + m] = W_out[t];
    }
    if (t < 22 * 64) g_Wot[170 * 64 + t] = 0.f;   // zero rows 170..191
}

// ---------------- K1: per-patch 2D DCT, register-resident ----------------
__global__ __launch_bounds__(256) void k_dct(const float* __restrict__ x) {
    __shared__ float Ms[64];
    int tid = threadIdx.x;
    if (tid < 64) {
        int i = tid >> 3, j = tid & 7;
        Ms[tid] = (i == 0) ? 0.35355339059327373f
                           : 0.5f * cospif((float)(i * (2 * j + 1)) * (1.0f / 16.0f));
    }
    __syncthreads();
    int pr = blockIdx.x * 8 + (tid >> 5);
    int pc = tid & 31;
    int c = blockIdx.y, b = blockIdx.z;
    const float* src = x + ((size_t)(b * CIN + c) * HH + pr * 8) * WW + pc * 8;
    float v[8][8];
    #pragma unroll
    for (int p = 0; p < 8; p++) {
        float4 a = *(const float4*)(src + (size_t)p * WW);
        float4 d = *(const float4*)(src + (size_t)p * WW + 4);
        v[p][0] = a.x; v[p][1] = a.y; v[p][2] = a.z; v[p][3] = a.w;
        v[p][4] = d.x; v[p][5] = d.y; v[p][6] = d.z; v[p][7] = d.w;
    }
    #pragma unroll
    for (int j = 0; j < 8; j++) {
        float u[8];
        #pragma unroll
        for (int p = 0; p < 8; p++) u[p] = v[p][j];
        #pragma unroll
        for (int i = 0; i < 8; i++) {
            float s = 0.f;
            #pragma unroll
            for (int p = 0; p < 8; p++) s += Ms[i * 8 + p] * u[p];
            v[i][j] = s;
        }
    }
    float* dst = g_xd + ((size_t)(b * CIN + c) * HH + pr * 8) * WW + pc * 8;
    #pragma unroll
    for (int i = 0; i < 8; i++) {
        float u[8];
        #pragma unroll
        for (int q = 0; q < 8; q++) u[q] = v[i][q];
        float y[8];
        #pragma unroll
        for (int j = 0; j < 8; j++) {
            float s = 0.f;
            #pragma unroll
            for (int q = 0; q < 8; q++) s += u[q] * Ms[j * 8 + q];
            y[j] = s;
        }
        *(float4*)(dst + (size_t)i * WW)     = make_float4(y[0], y[1], y[2], y[3]);
        *(float4*)(dst + (size_t)i * WW + 4) = make_float4(y[4], y[5], y[6], y[7]);
    }
}

// ---------------- K2: yq = quant * (W_in @ xd), split-tf32 mma ----------------
#define AS_STRIDE 68
#define BS_STRIDE 132
__global__ __launch_bounds__(256) void k_proj_in(const float* __restrict__ quant) {
    __shared__ float As[64 * AS_STRIDE];   // [k][m] fp32, padded
    __shared__ float Bs[64 * BS_STRIDE];   // [k][n] fp32, padded
    int m0 = blockIdx.x * 64;
    int n0 = blockIdx.y * 128;
    int b  = blockIdx.z;
    int tid = threadIdx.x;

    for (int i = tid; i < 64 * 16; i += 256) {
        int k = i >> 4, m4 = (i & 15) * 4;
        *(float4*)&As[k * AS_STRIDE + m4] = *(const float4*)(g_Wt + k * 384 + m0 + m4);
    }
    const float* Bbase = g_xd + (size_t)b * CIN * NPIX + n0;
    for (int i = tid; i < 64 * 32; i += 256) {
        int k = i >> 5, n4 = (i & 31) * 4;
        *(float4*)&Bs[k * BS_STRIDE + n4] = *(const float4*)(Bbase + (size_t)k * NPIX + n4);
    }
    __syncthreads();

    int warp = tid >> 5, lane = tid & 31;
    int wm = warp & 1, wn = warp >> 1;
    int g  = lane >> 2, tg = lane & 3;
    int mb = wm * 32, nb = wn * 32;

    float c[2][4][4];
    #pragma unroll
    for (int mi = 0; mi < 2; mi++)
        #pragma unroll
        for (int ni = 0; ni < 4; ni++)
            #pragma unroll
            for (int t = 0; t < 4; t++) c[mi][ni][t] = 0.f;

    #pragma unroll
    for (int ks = 0; ks < 8; ks++) {
        int k0 = ks * 8;
        unsigned ah[2][4], al[2][4];
        #pragma unroll
        for (int mi = 0; mi < 2; mi++) {
            int mloc = mb + mi * 16;
            float a0 = As[(k0 + tg)     * AS_STRIDE + mloc + g];
            float a1 = As[(k0 + tg)     * AS_STRIDE + mloc + g + 8];
            float a2 = As[(k0 + tg + 4) * AS_STRIDE + mloc + g];
            float a3 = As[(k0 + tg + 4) * AS_STRIDE + mloc + g + 8];
            tfsplit(a0, ah[mi][0], al[mi][0]);
            tfsplit(a1, ah[mi][1], al[mi][1]);
            tfsplit(a2, ah[mi][2], al[mi][2]);
            tfsplit(a3, ah[mi][3], al[mi][3]);
        }
        #pragma unroll
        for (int ni = 0; ni < 4; ni++) {
            int nloc = nb + ni * 8;
            float bf0 = Bs[(k0 + tg)     * BS_STRIDE + nloc + g];
            float bf1 = Bs[(k0 + tg + 4) * BS_STRIDE + nloc + g];
            unsigned bh0, bl0, bh1, bl1;
            tfsplit(bf0, bh0, bl0);
            tfsplit(bf1, bh1, bl1);
            #pragma unroll
            for (int mi = 0; mi < 2; mi++) {
                MMA_TF32(c[mi][ni], ah[mi][0], ah[mi][1], ah[mi][2], ah[mi][3], bl0, bl1);
                MMA_TF32(c[mi][ni], al[mi][0], al[mi][1], al[mi][2], al[mi][3], bh0, bh1);
                MMA_TF32(c[mi][ni], ah[mi][0], ah[mi][1], ah[mi][2], ah[mi][3], bh0, bh1);
            }
        }
    }

    int fi = (n0 >> 8) & 7;
    float* outb = g_yq + (size_t)b * C2 * NPIX + n0;
    #pragma unroll
    for (int mi = 0; mi < 2; mi++) {
        #pragma unroll
        for (int half = 0; half < 2; half++) {
            int cc = m0 + mb + mi * 16 + g + half * 8;
            if (cc < C2) {
                const float* qrow = quant + cc * 64 + fi * 8;
                float* orow = outb + (size_t)cc * NPIX;
                #pragma unroll
                for (int ni = 0; ni < 4; ni++) {
                    int nloc = nb + ni * 8 + 2 * tg;
                    int fj = 2 * tg;
                    float2 o;
                    o.x = c[mi][ni][half * 2]     * qrow[fj];
                    o.y = c[mi][ni][half * 2 + 1] * qrow[fj + 1];
                    *(float2*)(orow + nloc) = o;
                }
            }
        }
    }
}

// ---------------- K3: fused IDCT + depthwise 3x3 + GLU(gelu) -> g ----------------
__global__ __launch_bounds__(384) void k_fuse(const float* __restrict__ W_dw) {
    extern __shared__ float sm[];                  // 96 rows * 256 floats = 96 KB
    __shared__ float Ms[64];
    int tid = threadIdx.x;
    if (tid < 64) {
        int i = tid >> 3, j = tid & 7;
        Ms[tid] = (i == 0) ? 0.35355339059327373f
                           : 0.5f * cospif((float)(i * (2 * j + 1)) * (1.0f / 16.0f));
    }
    __syncthreads();

    int yt = blockIdx.x, c = blockIdx.y, b = blockIdx.z;
    int y0 = yt * 32;

    {
        int ch  = tid / 192;
        int rem = tid - ch * 192;
        int pr  = rem >> 5;
        int pc  = rem & 31;
        const float* src = g_yq + (size_t)(b * C2 + c + ch * HID) * NPIX;
        int gy0 = y0 - 8 + pr * 8;
        float v[8][8];
        if (gy0 >= 0 && gy0 < HH) {
            #pragma unroll
            for (int p = 0; p < 8; p++) {
                const float* row = src + (size_t)(gy0 + p) * WW + pc * 8;
                float4 a = *(const float4*)row;
                float4 d = *(const float4*)(row + 4);
                v[p][0] = a.x; v[p][1] = a.y; v[p][2] = a.z; v[p][3] = a.w;
                v[p][4] = d.x; v[p][5] = d.y; v[p][6] = d.z; v[p][7] = d.w;
            }
            #pragma unroll
            for (int j = 0; j < 8; j++) {
                float u[8];
                #pragma unroll
                for (int p = 0; p < 8; p++) u[p] = v[p][j];
                #pragma unroll
                for (int r = 0; r < 8; r++) {
                    float s = 0.f;
                    #pragma unroll
                    for (int p = 0; p < 8; p++) s += Ms[p * 8 + r] * u[p];
                    v[r][j] = s;
                }
            }
            #pragma unroll
            for (int r = 0; r < 8; r++) {
                float u[8];
                #pragma unroll
                for (int q = 0; q < 8; q++) u[q] = v[r][q];
                #pragma unroll
                for (int j = 0; j < 8; j++) {
                    float s = 0.f;
                    #pragma unroll
                    for (int q = 0; q < 8; q++) s += u[q] * Ms[q * 8 + j];
                    v[r][j] = s;
                }
            }
        } else {
            #pragma unroll
            for (int p = 0; p < 8; p++)
                #pragma unroll
                for (int j = 0; j < 8; j++) v[p][j] = 0.f;
        }
        float* dst = &sm[(ch * 48 + pr * 8) * 256 + pc * 8];
        #pragma unroll
        for (int r = 0; r < 8; r++) {
            *(float4*)(dst + r * 256)     = make_float4(v[r][0], v[r][1], v[r][2], v[r][3]);
            *(float4*)(dst + r * 256 + 4) = make_float4(v[r][4], v[r][5], v[r][6], v[r][7]);
        }
    }
    __syncthreads();

    float wA[9], wB[9];
    #pragma unroll
    for (int t = 0; t < 9; t++) wA[t] = __ldg(&W_dw[c * 9 + t]);
    #pragma unroll
    for (int t = 0; t < 9; t++) wB[t] = __ldg(&W_dw[(c + HID) * 9 + t]);

    float* gdst = g_g + (size_t)(b * HID + c) * NPIX + (size_t)y0 * WW;
    for (int g4 = tid; g4 < 32 * 64; g4 += 384) {
        int r = g4 >> 6, w0 = (g4 & 63) * 4;
        float s1[4] = {0.f, 0.f, 0.f, 0.f};
        float s2[4] = {0.f, 0.f, 0.f, 0.f};
        #pragma unroll
        for (int dy = 0; dy < 3; dy++) {
            const float* rowA = &sm[(r + 7 + dy) * 256];
            const float* rowB = rowA + 48 * 256;
            // vectorized window load: 1 LDS.128 + 2 scalar per channel
            float4 mA = *(const float4*)(rowA + w0);
            float4 mB = *(const float4*)(rowB + w0);
            float lA = (w0 == 0)   ? 0.f : rowA[w0 - 1];
            float rA = (w0 == 252) ? 0.f : rowA[w0 + 4];
            float lB = (w0 == 0)   ? 0.f : rowB[w0 - 1];
            float rB = (w0 == 252) ? 0.f : rowB[w0 + 4];
            float vA[6] = {lA, mA.x, mA.y, mA.z, mA.w, rA};
            float vB[6] = {lB, mB.x, mB.y, mB.z, mB.w, rB};
            #pragma unroll
            for (int dx = 0; dx < 3; dx++) {
                float wa = wA[dy * 3 + dx], wb = wB[dy * 3 + dx];
                #pragma unroll
                for (int j = 0; j < 4; j++) {
                    s1[j] += wa * vA[j + dx];
                    s2[j] += wb * vB[j + dx];
                }
            }
        }
        float o[4];
        #pragma unroll
        for (int j = 0; j < 4; j++)
            o[j] = 0.5f * s1[j] * (1.f + erff(s1[j] * 0.70710678118654752f)) * s2[j];
        *(float4*)&gdst[r * 256 + w0] = make_float4(o[0], o[1], o[2], o[3]);
    }
}

// ---------------- K4: out = W_out @ g, split-tf32 mma ----------------
// M=64, N=65536, K=170 padded to 192 (3 chunks of 64). Block 64M x 128N.
__global__ __launch_bounds__(256) void k_proj_out(float* __restrict__ out) {
    __shared__ float As[64 * AS_STRIDE];   // [k][m] fp32, padded
    __shared__ float Bs[64 * BS_STRIDE];   // [k][n] fp32, padded
    int n0 = blockIdx.x * 128;
    int b  = blockIdx.y;
    int tid = threadIdx.x;

    int warp = tid >> 5, lane = tid & 31;
    int wm = warp & 1, wn = warp >> 1;
    int g  = lane >> 2, tg = lane & 3;
    int mb = wm * 32, nb = wn * 32;

    float c[2][4][4];
    #pragma unroll
    for (int mi = 0; mi < 2; mi++)
        #pragma unroll
        for (int ni = 0; ni < 4; ni++)
            #pragma unroll
            for (int t = 0; t < 4; t++) c[mi][ni][t] = 0.f;

    for (int kk = 0; kk < 192; kk += 64) {
        for (int i = tid; i < 64 * 16; i += 256) {
            int k = i >> 4, m4 = (i & 15) * 4;
            *(float4*)&As[k * AS_STRIDE + m4] = *(const float4*)(g_Wot + (kk + k) * 64 + m4);
        }
        for (int i = tid; i < 64 * 32; i += 256) {
            int k = i >> 5, n4 = (i & 31) * 4;
            float4 v = make_float4(0.f, 0.f, 0.f, 0.f);
            if (kk + k < HID)
                v = *(const float4*)(g_g + (size_t)(b * HID + kk + k) * NPIX + n0 + n4);
            *(float4*)&Bs[k * BS_STRIDE + n4] = v;
        }
        __syncthreads();

        #pragma unroll
        for (int ks = 0; ks < 8; ks++) {
            int k0 = ks * 8;
            unsigned ah[2][4], al[2][4];
            #pragma unroll
            for (int mi = 0; mi < 2; mi++) {
                int mloc = mb + mi * 16;
                float a0 = As[(k0 + tg)     * AS_STRIDE + mloc + g];
                float a1 = As[(k0 + tg)     * AS_STRIDE + mloc + g + 8];
                float a2 = As[(k0 + tg + 4) * AS_STRIDE + mloc + g];
                float a3 = As[(k0 + tg + 4) * AS_STRIDE + mloc + g + 8];
                tfsplit(a0, ah[mi][0], al[mi][0]);
                tfsplit(a1, ah[mi][1], al[mi][1]);
                tfsplit(a2, ah[mi][2], al[mi][2]);
                tfsplit(a3, ah[mi][3], al[mi][3]);
            }
            #pragma unroll
            for (int ni = 0; ni < 4; ni++) {
                int nloc = nb + ni * 8;
                float bf0 = Bs[(k0 + tg)     * BS_STRIDE + nloc + g];
                float bf1 = Bs[(k0 + tg + 4) * BS_STRIDE + nloc + g];
                unsigned bh0, bl0, bh1, bl1;
                tfsplit(bf0, bh0, bl0);
                tfsplit(bf1, bh1, bl1);
                #pragma unroll
                for (int mi = 0; mi < 2; mi++) {
                    MMA_TF32(c[mi][ni], ah[mi][0], ah[mi][1], ah[mi][2], ah[mi][3], bl0, bl1);
                    MMA_TF32(c[mi][ni], al[mi][0], al[mi][1], al[mi][2], al[mi][3], bh0, bh1);
                    MMA_TF32(c[mi][ni], ah[mi][0], ah[mi][1], ah[mi][2], ah[mi][3], bh0, bh1);
                }
            }
        }
        __syncthreads();
    }

    float* outb = out + (size_t)b * 64 * NPIX + n0;
    #pragma unroll
    for (int mi = 0; mi < 2; mi++) {
        #pragma unroll
        for (int half = 0; half < 2; half++) {
            int cc = mb + mi * 16 + g + half * 8;      // 0..63, all valid
            float* orow = outb + (size_t)cc * NPIX;
            #pragma unroll
            for (int ni = 0; ni < 4; ni++) {
                int nloc = nb + ni * 8 + 2 * tg;
                float2 o;
                o.x = c[mi][ni][half * 2];
                o.y = c[mi][ni][half * 2 + 1];
                *(float2*)(orow + nloc) = o;
            }
        }
    }
}

// ---------------- launch ----------------
extern "C" void kernel_launch(void* const* d_in, const int* in_sizes, int n_in,
                              void* d_out, int out_size) {
    (void)in_sizes; (void)n_in; (void)out_size;
    const float* x     = (const float*)d_in[0];
    const float* W_in  = (const float*)d_in[1];
    const float* W_dw  = (const float*)d_in[2];
    const float* quant = (const float*)d_in[3];
    const float* W_out = (const float*)d_in[4];
    float* out = (float*)d_out;

    cudaFuncSetAttribute(k_fuse, cudaFuncAttributeMaxDynamicSharedMemorySize,
                         96 * 256 * 4);

    k_transpose<<<85, 256>>>(W_in, W_out);
    k_dct<<<dim3(4, 64, 4), 256>>>(x);
    k_proj_in<<<dim3(6, 512, 4), 256>>>(quant);
    k_fuse<<<dim3(8, 170, 4), 384, 96 * 256 * 4>>>(W_dw);
    k_proj_out<<<dim3(512, 4), 256>>>(out);
}

// round 14
// speedup vs baseline: 1.4643x; 1.4643x over previous
#include <cuda_runtime.h>
#include <math.h>

#define BB   4
#define CIN  64
#define C2   340
#define HID  170
#define HH   256
#define WW   256
#define NPIX 65536   /* 256*256 */

// ---------------- scratch (device globals; no allocations) ----------------
__device__ float g_xd[BB * CIN * NPIX];          // DCT(x): 67 MB
__device__ float g_yq[BB * C2  * NPIX];          // quant * (W_in @ DCT(x)): 356 MB
__device__ float g_g [BB * HID * NPIX];          // gelu(x1)*x2: 178 MB
__device__ float g_Wt_hi[64 * 384];              // W_in^T  hi (tf32-exact), [k][m]
__device__ float g_Wt_lo[64 * 384];              // W_in^T  lo
__device__ float g_Wot_hi[192 * 64];             // W_out^T hi, K padded 170->192
__device__ float g_Wot_lo[192 * 64];             // W_out^T lo

__device__ __forceinline__ unsigned f2tf(float f) {
    unsigned u;
    asm("cvt.rna.tf32.f32 %0, %1;" : "=r"(u) : "f"(f));
    return u;
}

#define MMA_TF32(C, A0, A1, A2, A3, B0, B1)                                  \
    asm("mma.sync.aligned.m16n8k8.row.col.f32.tf32.tf32.f32 "                \
        "{%0,%1,%2,%3}, {%4,%5,%6,%7}, {%8,%9}, {%0,%1,%2,%3};"              \
        : "+f"(C[0]), "+f"(C[1]), "+f"(C[2]), "+f"(C[3])                     \
        : "r"(A0), "r"(A1), "r"(A2), "r"(A3), "r"(B0), "r"(B1))

// ---------------- weight transpose + offline tf32 hi/lo split ----------------
__global__ void k_transpose(const float* __restrict__ W_in,
                            const float* __restrict__ W_out) {
    int t = blockIdx.x * blockDim.x + threadIdx.x;
    if (t < C2 * CIN) {               // W_in [340][64] -> [64][384] hi/lo
        int m = t / CIN, k = t % CIN;
        float w  = W_in[t];
        float hi = __uint_as_float(f2tf(w));
        g_Wt_hi[k * 384 + m] = hi;
        g_Wt_lo[k * 384 + m] = __uint_as_float(f2tf(w - hi));
    }
    if (t < 64 * HID) {               // W_out [64][170] -> [170][64] hi/lo
        int m = t / HID, k = t % HID;
        float w  = W_out[t];
        float hi = __uint_as_float(f2tf(w));
        g_Wot_hi[k * 64 + m] = hi;
        g_Wot_lo[k * 64 + m] = __uint_as_float(f2tf(w - hi));
    }
    if (t < 22 * 64) {                // zero pad rows 170..191
        g_Wot_hi[170 * 64 + t] = 0.f;
        g_Wot_lo[170 * 64 + t] = 0.f;
    }
}

// ---------------- K1: per-patch 2D DCT, register-resident ----------------
__global__ __launch_bounds__(256) void k_dct(const float* __restrict__ x) {
    __shared__ float Ms[64];
    int tid = threadIdx.x;
    if (tid < 64) {
        int i = tid >> 3, j = tid & 7;
        Ms[tid] = (i == 0) ? 0.35355339059327373f
                           : 0.5f * cospif((float)(i * (2 * j + 1)) * (1.0f / 16.0f));
    }
    __syncthreads();
    int pr = blockIdx.x * 8 + (tid >> 5);
    int pc = tid & 31;
    int c = blockIdx.y, b = blockIdx.z;
    const float* src = x + ((size_t)(b * CIN + c) * HH + pr * 8) * WW + pc * 8;
    float v[8][8];
    #pragma unroll
    for (int p = 0; p < 8; p++) {
        float4 a = *(const float4*)(src + (size_t)p * WW);
        float4 d = *(const float4*)(src + (size_t)p * WW + 4);
        v[p][0] = a.x; v[p][1] = a.y; v[p][2] = a.z; v[p][3] = a.w;
        v[p][4] = d.x; v[p][5] = d.y; v[p][6] = d.z; v[p][7] = d.w;
    }
    #pragma unroll
    for (int j = 0; j < 8; j++) {
        float u[8];
        #pragma unroll
        for (int p = 0; p < 8; p++) u[p] = v[p][j];
        #pragma unroll
        for (int i = 0; i < 8; i++) {
            float s = 0.f;
            #pragma unroll
            for (int p = 0; p < 8; p++) s += Ms[i * 8 + p] * u[p];
            v[i][j] = s;
        }
    }
    float* dst = g_xd + ((size_t)(b * CIN + c) * HH + pr * 8) * WW + pc * 8;
    #pragma unroll
    for (int i = 0; i < 8; i++) {
        float u[8];
        #pragma unroll
        for (int q = 0; q < 8; q++) u[q] = v[i][q];
        float y[8];
        #pragma unroll
        for (int j = 0; j < 8; j++) {
            float s = 0.f;
            #pragma unroll
            for (int q = 0; q < 8; q++) s += u[q] * Ms[j * 8 + q];
            y[j] = s;
        }
        *(float4*)(dst + (size_t)i * WW)     = make_float4(y[0], y[1], y[2], y[3]);
        *(float4*)(dst + (size_t)i * WW + 4) = make_float4(y[4], y[5], y[6], y[7]);
    }
}

// ---------------- K2: yq = quant * (W_in @ xd), 2-MMA split-A tf32 ----------------
#define AS_STRIDE 68
#define BS_STRIDE 132
__global__ __launch_bounds__(256) void k_proj_in(const float* __restrict__ quant) {
    __shared__ unsigned Ah[64 * AS_STRIDE];   // [k][m] tf32 hi
    __shared__ unsigned Al[64 * AS_STRIDE];   // [k][m] tf32 lo
    __shared__ unsigned Bs[64 * BS_STRIDE];   // [k][n] tf32 hi
    int m0 = blockIdx.x * 64;
    int n0 = blockIdx.y * 128;
    int b  = blockIdx.z;
    int tid = threadIdx.x;

    for (int i = tid; i < 64 * 16; i += 256) {
        int k = i >> 4, m4 = (i & 15) * 4;
        float4 h = *(const float4*)(g_Wt_hi + k * 384 + m0 + m4);
        float4 l = *(const float4*)(g_Wt_lo + k * 384 + m0 + m4);
        unsigned* dh = &Ah[k * AS_STRIDE + m4];
        unsigned* dl = &Al[k * AS_STRIDE + m4];
        dh[0] = __float_as_uint(h.x); dh[1] = __float_as_uint(h.y);
        dh[2] = __float_as_uint(h.z); dh[3] = __float_as_uint(h.w);
        dl[0] = __float_as_uint(l.x); dl[1] = __float_as_uint(l.y);
        dl[2] = __float_as_uint(l.z); dl[3] = __float_as_uint(l.w);
    }
    const float* Bbase = g_xd + (size_t)b * CIN * NPIX + n0;
    for (int i = tid; i < 64 * 32; i += 256) {
        int k = i >> 5, n4 = (i & 31) * 4;
        float4 w = *(const float4*)(Bbase + (size_t)k * NPIX + n4);
        unsigned* d = &Bs[k * BS_STRIDE + n4];
        d[0] = f2tf(w.x); d[1] = f2tf(w.y); d[2] = f2tf(w.z); d[3] = f2tf(w.w);
    }
    __syncthreads();

    int warp = tid >> 5, lane = tid & 31;
    int wm = warp & 1, wn = warp >> 1;
    int g  = lane >> 2, tg = lane & 3;
    int mb = wm * 32, nb = wn * 32;

    float c[2][4][4];
    #pragma unroll
    for (int mi = 0; mi < 2; mi++)
        #pragma unroll
        for (int ni = 0; ni < 4; ni++)
            #pragma unroll
            for (int t = 0; t < 4; t++) c[mi][ni][t] = 0.f;

    #pragma unroll
    for (int ks = 0; ks < 8; ks++) {
        int k0 = ks * 8;
        unsigned ah[2][4], al[2][4];
        #pragma unroll
        for (int mi = 0; mi < 2; mi++) {
            int mloc = mb + mi * 16;
            ah[mi][0] = Ah[(k0 + tg)     * AS_STRIDE + mloc + g];
            ah[mi][1] = Ah[(k0 + tg)     * AS_STRIDE + mloc + g + 8];
            ah[mi][2] = Ah[(k0 + tg + 4) * AS_STRIDE + mloc + g];
            ah[mi][3] = Ah[(k0 + tg + 4) * AS_STRIDE + mloc + g + 8];
            al[mi][0] = Al[(k0 + tg)     * AS_STRIDE + mloc + g];
            al[mi][1] = Al[(k0 + tg)     * AS_STRIDE + mloc + g + 8];
            al[mi][2] = Al[(k0 + tg + 4) * AS_STRIDE + mloc + g];
            al[mi][3] = Al[(k0 + tg + 4) * AS_STRIDE + mloc + g + 8];
        }
        #pragma unroll
        for (int ni = 0; ni < 4; ni++) {
            int nloc = nb + ni * 8;
            unsigned b0 = Bs[(k0 + tg)     * BS_STRIDE + nloc + g];
            unsigned b1 = Bs[(k0 + tg + 4) * BS_STRIDE + nloc + g];
            #pragma unroll
            for (int mi = 0; mi < 2; mi++) {
                MMA_TF32(c[mi][ni], al[mi][0], al[mi][1], al[mi][2], al[mi][3], b0, b1);
                MMA_TF32(c[mi][ni], ah[mi][0], ah[mi][1], ah[mi][2], ah[mi][3], b0, b1);
            }
        }
    }

    int fi = (n0 >> 8) & 7;
    float* outb = g_yq + (size_t)b * C2 * NPIX + n0;
    #pragma unroll
    for (int mi = 0; mi < 2; mi++) {
        #pragma unroll
        for (int half = 0; half < 2; half++) {
            int cc = m0 + mb + mi * 16 + g + half * 8;
            if (cc < C2) {
                const float* qrow = quant + cc * 64 + fi * 8;
                float* orow = outb + (size_t)cc * NPIX;
                #pragma unroll
                for (int ni = 0; ni < 4; ni++) {
                    int nloc = nb + ni * 8 + 2 * tg;
                    int fj = 2 * tg;
                    float2 o;
                    o.x = c[mi][ni][half * 2]     * qrow[fj];
                    o.y = c[mi][ni][half * 2 + 1] * qrow[fj + 1];
                    *(float2*)(orow + nloc) = o;
                }
            }
        }
    }
}

// ---------------- K3: fused IDCT + depthwise 3x3 + GLU(gelu) -> g ----------------
// R10/R11 body verbatim (scalar conv loads — the R12 "vectorized" variant regressed).
__global__ __launch_bounds__(384) void k_fuse(const float* __restrict__ W_dw) {
    extern __shared__ float sm[];                  // 96 rows * 256 floats = 96 KB
    __shared__ float Ms[64];
    int tid = threadIdx.x;
    if (tid < 64) {
        int i = tid >> 3, j = tid & 7;
        Ms[tid] = (i == 0) ? 0.35355339059327373f
                           : 0.5f * cospif((float)(i * (2 * j + 1)) * (1.0f / 16.0f));
    }
    __syncthreads();

    int yt = blockIdx.x, c = blockIdx.y, b = blockIdx.z;
    int y0 = yt * 32;

    {
        int ch  = tid / 192;
        int rem = tid - ch * 192;
        int pr  = rem >> 5;
        int pc  = rem & 31;
        const float* src = g_yq + (size_t)(b * C2 + c + ch * HID) * NPIX;
        int gy0 = y0 - 8 + pr * 8;
        float v[8][8];
        if (gy0 >= 0 && gy0 < HH) {
            #pragma unroll
            for (int p = 0; p < 8; p++) {
                const float* row = src + (size_t)(gy0 + p) * WW + pc * 8;
                float4 a = *(const float4*)row;
                float4 d = *(const float4*)(row + 4);
                v[p][0] = a.x; v[p][1] = a.y; v[p][2] = a.z; v[p][3] = a.w;
                v[p][4] = d.x; v[p][5] = d.y; v[p][6] = d.z; v[p][7] = d.w;
            }
            #pragma unroll
            for (int j = 0; j < 8; j++) {
                float u[8];
                #pragma unroll
                for (int p = 0; p < 8; p++) u[p] = v[p][j];
                #pragma unroll
                for (int r = 0; r < 8; r++) {
                    float s = 0.f;
                    #pragma unroll
                    for (int p = 0; p < 8; p++) s += Ms[p * 8 + r] * u[p];
                    v[r][j] = s;
                }
            }
            #pragma unroll
            for (int r = 0; r < 8; r++) {
                float u[8];
                #pragma unroll
                for (int q = 0; q < 8; q++) u[q] = v[r][q];
                #pragma unroll
                for (int j = 0; j < 8; j++) {
                    float s = 0.f;
                    #pragma unroll
                    for (int q = 0; q < 8; q++) s += u[q] * Ms[q * 8 + j];
                    v[r][j] = s;
                }
            }
        } else {
            #pragma unroll
            for (int p = 0; p < 8; p++)
                #pragma unroll
                for (int j = 0; j < 8; j++) v[p][j] = 0.f;
        }
        float* dst = &sm[(ch * 48 + pr * 8) * 256 + pc * 8];
        #pragma unroll
        for (int r = 0; r < 8; r++) {
            *(float4*)(dst + r * 256)     = make_float4(v[r][0], v[r][1], v[r][2], v[r][3]);
            *(float4*)(dst + r * 256 + 4) = make_float4(v[r][4], v[r][5], v[r][6], v[r][7]);
        }
    }
    __syncthreads();

    float wA[9], wB[9];
    #pragma unroll
    for (int t = 0; t < 9; t++) wA[t] = __ldg(&W_dw[c * 9 + t]);
    #pragma unroll
    for (int t = 0; t < 9; t++) wB[t] = __ldg(&W_dw[(c + HID) * 9 + t]);

    float* gdst = g_g + (size_t)(b * HID + c) * NPIX + (size_t)y0 * WW;
    for (int g4 = tid; g4 < 32 * 64; g4 += 384) {
        int r = g4 >> 6, w0 = (g4 & 63) * 4;
        float s1[4] = {0.f, 0.f, 0.f, 0.f};
        float s2[4] = {0.f, 0.f, 0.f, 0.f};
        #pragma unroll
        for (int dy = 0; dy < 3; dy++) {
            const float* rowA = &sm[(r + 7 + dy) * 256];
            const float* rowB = rowA + 48 * 256;
            float vA[6], vB[6];
            vA[0] = (w0 == 0)   ? 0.f : rowA[w0 - 1];
            vA[1] = rowA[w0];     vA[2] = rowA[w0 + 1];
            vA[3] = rowA[w0 + 2]; vA[4] = rowA[w0 + 3];
            vA[5] = (w0 == 252) ? 0.f : rowA[w0 + 4];
            vB[0] = (w0 == 0)   ? 0.f : rowB[w0 - 1];
            vB[1] = rowB[w0];     vB[2] = rowB[w0 + 1];
            vB[3] = rowB[w0 + 2]; vB[4] = rowB[w0 + 3];
            vB[5] = (w0 == 252) ? 0.f : rowB[w0 + 4];
            #pragma unroll
            for (int dx = 0; dx < 3; dx++) {
                float wa = wA[dy * 3 + dx], wb = wB[dy * 3 + dx];
                #pragma unroll
                for (int j = 0; j < 4; j++) {
                    s1[j] += wa * vA[j + dx];
                    s2[j] += wb * vB[j + dx];
                }
            }
        }
        float o[4];
        #pragma unroll
        for (int j = 0; j < 4; j++)
            o[j] = 0.5f * s1[j] * (1.f + erff(s1[j] * 0.70710678118654752f)) * s2[j];
        *(float4*)&gdst[r * 256 + w0] = make_float4(o[0], o[1], o[2], o[3]);
    }
}

// ---------------- K4: out = W_out @ g, 2-MMA split-A tf32 ----------------
// M=64, N=65536, K=170 padded to 192 (3 chunks of 64). Block 64M x 128N.
__global__ __launch_bounds__(256) void k_proj_out(float* __restrict__ out) {
    __shared__ unsigned Ah[64 * AS_STRIDE];
    __shared__ unsigned Al[64 * AS_STRIDE];
    __shared__ unsigned Bs[64 * BS_STRIDE];
    int n0 = blockIdx.x * 128;
    int b  = blockIdx.y;
    int tid = threadIdx.x;

    int warp = tid >> 5, lane = tid & 31;
    int wm = warp & 1, wn = warp >> 1;
    int g  = lane >> 2, tg = lane & 3;
    int mb = wm * 32, nb = wn * 32;

    float c[2][4][4];
    #pragma unroll
    for (int mi = 0; mi < 2; mi++)
        #pragma unroll
        for (int ni = 0; ni < 4; ni++)
            #pragma unroll
            for (int t = 0; t < 4; t++) c[mi][ni][t] = 0.f;

    for (int kk = 0; kk < 192; kk += 64) {
        for (int i = tid; i < 64 * 16; i += 256) {
            int k = i >> 4, m4 = (i & 15) * 4;
            float4 h = *(const float4*)(g_Wot_hi + (kk + k) * 64 + m4);
            float4 l = *(const float4*)(g_Wot_lo + (kk + k) * 64 + m4);
            unsigned* dh = &Ah[k * AS_STRIDE + m4];
            unsigned* dl = &Al[k * AS_STRIDE + m4];
            dh[0] = __float_as_uint(h.x); dh[1] = __float_as_uint(h.y);
            dh[2] = __float_as_uint(h.z); dh[3] = __float_as_uint(h.w);
            dl[0] = __float_as_uint(l.x); dl[1] = __float_as_uint(l.y);
            dl[2] = __float_as_uint(l.z); dl[3] = __float_as_uint(l.w);
        }
        for (int i = tid; i < 64 * 32; i += 256) {
            int k = i >> 5, n4 = (i & 31) * 4;
            float4 v = make_float4(0.f, 0.f, 0.f, 0.f);
            if (kk + k < HID)
                v = *(const float4*)(g_g + (size_t)(b * HID + kk + k) * NPIX + n0 + n4);
            unsigned* d = &Bs[k * BS_STRIDE + n4];
            d[0] = f2tf(v.x); d[1] = f2tf(v.y); d[2] = f2tf(v.z); d[3] = f2tf(v.w);
        }
        __syncthreads();

        #pragma unroll
        for (int ks = 0; ks < 8; ks++) {
            int k0 = ks * 8;
            unsigned ah[2][4], al[2][4];
            #pragma unroll
            for (int mi = 0; mi < 2; mi++) {
                int mloc = mb + mi * 16;
                ah[mi][0] = Ah[(k0 + tg)     * AS_STRIDE + mloc + g];
                ah[mi][1] = Ah[(k0 + tg)     * AS_STRIDE + mloc + g + 8];
                ah[mi][2] = Ah[(k0 + tg + 4) * AS_STRIDE + mloc + g];
                ah[mi][3] = Ah[(k0 + tg + 4) * AS_STRIDE + mloc + g + 8];
                al[mi][0] = Al[(k0 + tg)     * AS_STRIDE + mloc + g];
                al[mi][1] = Al[(k0 + tg)     * AS_STRIDE + mloc + g + 8];
                al[mi][2] = Al[(k0 + tg + 4) * AS_STRIDE + mloc + g];
                al[mi][3] = Al[(k0 + tg + 4) * AS_STRIDE + mloc + g + 8];
            }
            #pragma unroll
            for (int ni = 0; ni < 4; ni++) {
                int nloc = nb + ni * 8;
                unsigned b0 = Bs[(k0 + tg)     * BS_STRIDE + nloc + g];
                unsigned b1 = Bs[(k0 + tg + 4) * BS_STRIDE + nloc + g];
                #pragma unroll
                for (int mi = 0; mi < 2; mi++) {
                    MMA_TF32(c[mi][ni], al[mi][0], al[mi][1], al[mi][2], al[mi][3], b0, b1);
                    MMA_TF32(c[mi][ni], ah[mi][0], ah[mi][1], ah[mi][2], ah[mi][3], b0, b1);
                }
            }
        }
        __syncthreads();
    }

    float* outb = out + (size_t)b * 64 * NPIX + n0;
    #pragma unroll
    for (int mi = 0; mi < 2; mi++) {
        #pragma unroll
        for (int half = 0; half < 2; half++) {
            int cc = mb + mi * 16 + g + half * 8;      // 0..63, all valid
            float* orow = outb + (size_t)cc * NPIX;
            #pragma unroll
            for (int ni = 0; ni < 4; ni++) {
                int nloc = nb + ni * 8 + 2 * tg;
                float2 o;
                o.x = c[mi][ni][half * 2];
                o.y = c[mi][ni][half * 2 + 1];
                *(float2*)(orow + nloc) = o;
            }
        }
    }
}

// ---------------- launch ----------------
extern "C" void kernel_launch(void* const* d_in, const int* in_sizes, int n_in,
                              void* d_out, int out_size) {
    (void)in_sizes; (void)n_in; (void)out_size;
    const float* x     = (const float*)d_in[0];
    const float* W_in  = (const float*)d_in[1];
    const float* W_dw  = (const float*)d_in[2];
    const float* quant = (const float*)d_in[3];
    const float* W_out = (const float*)d_in[4];
    float* out = (float*)d_out;

    cudaFuncSetAttribute(k_fuse, cudaFuncAttributeMaxDynamicSharedMemorySize,
                         96 * 256 * 4);

    k_transpose<<<85, 256>>>(W_in, W_out);
    k_dct<<<dim3(4, 64, 4), 256>>>(x);
    k_proj_in<<<dim3(6, 512, 4), 256>>>(quant);
    k_fuse<<<dim3(8, 170, 4), 384, 96 * 256 * 4>>>(W_dw);
    k_proj_out<<<dim3(512, 4), 256>>>(out);
}

// round 15
// speedup vs baseline: 1.6697x; 1.1403x over previous
#include <cuda_runtime.h>
#include <math.h>

#define BB   4
#define CIN  64
#define C2   340
#define HID  170
#define HH   256
#define WW   256
#define NPIX 65536   /* 256*256 */

// ---------------- scratch (device globals; no allocations) ----------------
__device__ float g_xd[BB * CIN * NPIX];          // DCT(x): 67 MB
__device__ float g_yq[BB * C2  * NPIX];          // quant * (W_in @ DCT(x)): 356 MB
__device__ float g_g [BB * HID * NPIX];          // gelu(x1)*x2: 178 MB
__device__ float g_Wt [64  * 384];               // W_in^T  [k][m], stride 384 (zero padded BSS)
__device__ float g_Wot_hi[192 * 64];             // W_out^T hi, K padded 170->192
__device__ float g_Wot_lo[192 * 64];             // W_out^T lo

__device__ __forceinline__ unsigned f2tf(float f) {
    unsigned u;
    asm("cvt.rna.tf32.f32 %0, %1;" : "=r"(u) : "f"(f));
    return u;
}

#define MMA_TF32(C, A0, A1, A2, A3, B0, B1)                                  \
    asm("mma.sync.aligned.m16n8k8.row.col.f32.tf32.tf32.f32 "                \
        "{%0,%1,%2,%3}, {%4,%5,%6,%7}, {%8,%9}, {%0,%1,%2,%3};"              \
        : "+f"(C[0]), "+f"(C[1]), "+f"(C[2]), "+f"(C[3])                     \
        : "r"(A0), "r"(A1), "r"(A2), "r"(A3), "r"(B0), "r"(B1))

// ---------------- weight transpose; W_out also gets offline tf32 hi/lo split ----
__global__ void k_transpose(const float* __restrict__ W_in,
                            const float* __restrict__ W_out) {
    int t = blockIdx.x * blockDim.x + threadIdx.x;
    if (t < C2 * CIN) {               // W_in [340][64] -> g_Wt [64][384]
        int m = t / CIN, k = t % CIN;
        g_Wt[k * 384 + m] = W_in[t];
    }
    if (t < 64 * HID) {               // W_out [64][170] -> [170][64] hi/lo
        int m = t / HID, k = t % HID;
        float w  = W_out[t];
        float hi = __uint_as_float(f2tf(w));
        g_Wot_hi[k * 64 + m] = hi;
        g_Wot_lo[k * 64 + m] = __uint_as_float(f2tf(w - hi));
    }
    if (t < 22 * 64) {                // zero pad rows 170..191
        g_Wot_hi[170 * 64 + t] = 0.f;
        g_Wot_lo[170 * 64 + t] = 0.f;
    }
}

// ---------------- K1: per-patch 2D DCT, register-resident (R10, measured) ----------
__global__ __launch_bounds__(256) void k_dct(const float* __restrict__ x) {
    __shared__ float Ms[64];
    int tid = threadIdx.x;
    if (tid < 64) {
        int i = tid >> 3, j = tid & 7;
        Ms[tid] = (i == 0) ? 0.35355339059327373f
                           : 0.5f * cospif((float)(i * (2 * j + 1)) * (1.0f / 16.0f));
    }
    __syncthreads();
    int pr = blockIdx.x * 8 + (tid >> 5);
    int pc = tid & 31;
    int c = blockIdx.y, b = blockIdx.z;
    const float* src = x + ((size_t)(b * CIN + c) * HH + pr * 8) * WW + pc * 8;
    float v[8][8];
    #pragma unroll
    for (int p = 0; p < 8; p++) {
        float4 a = *(const float4*)(src + (size_t)p * WW);
        float4 d = *(const float4*)(src + (size_t)p * WW + 4);
        v[p][0] = a.x; v[p][1] = a.y; v[p][2] = a.z; v[p][3] = a.w;
        v[p][4] = d.x; v[p][5] = d.y; v[p][6] = d.z; v[p][7] = d.w;
    }
    #pragma unroll
    for (int j = 0; j < 8; j++) {
        float u[8];
        #pragma unroll
        for (int p = 0; p < 8; p++) u[p] = v[p][j];
        #pragma unroll
        for (int i = 0; i < 8; i++) {
            float s = 0.f;
            #pragma unroll
            for (int p = 0; p < 8; p++) s += Ms[i * 8 + p] * u[p];
            v[i][j] = s;
        }
    }
    float* dst = g_xd + ((size_t)(b * CIN + c) * HH + pr * 8) * WW + pc * 8;
    #pragma unroll
    for (int i = 0; i < 8; i++) {
        float u[8];
        #pragma unroll
        for (int q = 0; q < 8; q++) u[q] = v[i][q];
        float y[8];
        #pragma unroll
        for (int j = 0; j < 8; j++) {
            float s = 0.f;
            #pragma unroll
            for (int q = 0; q < 8; q++) s += u[q] * Ms[j * 8 + q];
            y[j] = s;
        }
        *(float4*)(dst + (size_t)i * WW)     = make_float4(y[0], y[1], y[2], y[3]);
        *(float4*)(dst + (size_t)i * WW + 4) = make_float4(y[4], y[5], y[6], y[7]);
    }
}

// ---------------- K2: yq = quant * (W_in @ xd), 1-MMA tf32 (R11, measured) --------
#define AS_STRIDE 68
#define BS_STRIDE 132
__global__ __launch_bounds__(256) void k_proj_in(const float* __restrict__ quant) {
    __shared__ unsigned As[64 * AS_STRIDE];   // [k][m], tf32, padded
    __shared__ unsigned Bs[64 * BS_STRIDE];   // [k][n], tf32, padded
    int m0 = blockIdx.x * 64;
    int n0 = blockIdx.y * 128;
    int b  = blockIdx.z;
    int tid = threadIdx.x;

    for (int i = tid; i < 64 * 16; i += 256) {            // A tile
        int k = i >> 4, m4 = (i & 15) * 4;
        float4 w = *(const float4*)(g_Wt + k * 384 + m0 + m4);
        unsigned* d = &As[k * AS_STRIDE + m4];
        d[0] = f2tf(w.x); d[1] = f2tf(w.y); d[2] = f2tf(w.z); d[3] = f2tf(w.w);
    }
    const float* Bbase = g_xd + (size_t)b * CIN * NPIX + n0;
    for (int i = tid; i < 64 * 32; i += 256) {            // B tile
        int k = i >> 5, n4 = (i & 31) * 4;
        float4 w = *(const float4*)(Bbase + (size_t)k * NPIX + n4);
        unsigned* d = &Bs[k * BS_STRIDE + n4];
        d[0] = f2tf(w.x); d[1] = f2tf(w.y); d[2] = f2tf(w.z); d[3] = f2tf(w.w);
    }
    __syncthreads();

    int warp = tid >> 5, lane = tid & 31;
    int wm = warp & 1, wn = warp >> 1;                    // 2 x 4 warp grid
    int g  = lane >> 2, tg = lane & 3;
    int mb = wm * 32, nb = wn * 32;

    float c[2][4][4];
    #pragma unroll
    for (int mi = 0; mi < 2; mi++)
        #pragma unroll
        for (int ni = 0; ni < 4; ni++)
            #pragma unroll
            for (int t = 0; t < 4; t++) c[mi][ni][t] = 0.f;

    #pragma unroll
    for (int ks = 0; ks < 8; ks++) {
        int k0 = ks * 8;
        unsigned a[2][4];
        #pragma unroll
        for (int mi = 0; mi < 2; mi++) {
            int mloc = mb + mi * 16;
            a[mi][0] = As[(k0 + tg)     * AS_STRIDE + mloc + g];
            a[mi][1] = As[(k0 + tg)     * AS_STRIDE + mloc + g + 8];
            a[mi][2] = As[(k0 + tg + 4) * AS_STRIDE + mloc + g];
            a[mi][3] = As[(k0 + tg + 4) * AS_STRIDE + mloc + g + 8];
        }
        #pragma unroll
        for (int ni = 0; ni < 4; ni++) {
            int nloc = nb + ni * 8;
            unsigned b0 = Bs[(k0 + tg)     * BS_STRIDE + nloc + g];
            unsigned b1 = Bs[(k0 + tg + 4) * BS_STRIDE + nloc + g];
            #pragma unroll
            for (int mi = 0; mi < 2; mi++) {
                MMA_TF32(c[mi][ni], a[mi][0], a[mi][1], a[mi][2], a[mi][3], b0, b1);
            }
        }
    }

    int fi = (n0 >> 8) & 7;
    float* outb = g_yq + (size_t)b * C2 * NPIX + n0;
    #pragma unroll
    for (int mi = 0; mi < 2; mi++) {
        #pragma unroll
        for (int half = 0; half < 2; half++) {
            int cc = m0 + mb + mi * 16 + g + half * 8;
            if (cc < C2) {
                const float* qrow = quant + cc * 64 + fi * 8;
                float* orow = outb + (size_t)cc * NPIX;
                #pragma unroll
                for (int ni = 0; ni < 4; ni++) {
                    int nloc = nb + ni * 8 + 2 * tg;
                    int fj = 2 * tg;
                    float2 o;
                    o.x = c[mi][ni][half * 2]     * qrow[fj];
                    o.y = c[mi][ni][half * 2 + 1] * qrow[fj + 1];
                    *(float2*)(orow + nloc) = o;
                }
            }
        }
    }
}

// ---------------- K3: fused IDCT + depthwise 3x3 + GLU(gelu) -> g (R10, measured) --
__global__ __launch_bounds__(384) void k_fuse(const float* __restrict__ W_dw) {
    extern __shared__ float sm[];                  // 96 rows * 256 floats = 96 KB
    __shared__ float Ms[64];
    int tid = threadIdx.x;
    if (tid < 64) {
        int i = tid >> 3, j = tid & 7;
        Ms[tid] = (i == 0) ? 0.35355339059327373f
                           : 0.5f * cospif((float)(i * (2 * j + 1)) * (1.0f / 16.0f));
    }
    __syncthreads();

    int yt = blockIdx.x, c = blockIdx.y, b = blockIdx.z;
    int y0 = yt * 32;

    {
        int ch  = tid / 192;
        int rem = tid - ch * 192;
        int pr  = rem >> 5;
        int pc  = rem & 31;
        const float* src = g_yq + (size_t)(b * C2 + c + ch * HID) * NPIX;
        int gy0 = y0 - 8 + pr * 8;
        float v[8][8];
        if (gy0 >= 0 && gy0 < HH) {
            #pragma unroll
            for (int p = 0; p < 8; p++) {
                const float* row = src + (size_t)(gy0 + p) * WW + pc * 8;
                float4 a = *(const float4*)row;
                float4 d = *(const float4*)(row + 4);
                v[p][0] = a.x; v[p][1] = a.y; v[p][2] = a.z; v[p][3] = a.w;
                v[p][4] = d.x; v[p][5] = d.y; v[p][6] = d.z; v[p][7] = d.w;
            }
            #pragma unroll
            for (int j = 0; j < 8; j++) {
                float u[8];
                #pragma unroll
                for (int p = 0; p < 8; p++) u[p] = v[p][j];
                #pragma unroll
                for (int r = 0; r < 8; r++) {
                    float s = 0.f;
                    #pragma unroll
                    for (int p = 0; p < 8; p++) s += Ms[p * 8 + r] * u[p];
                    v[r][j] = s;
                }
            }
            #pragma unroll
            for (int r = 0; r < 8; r++) {
                float u[8];
                #pragma unroll
                for (int q = 0; q < 8; q++) u[q] = v[r][q];
                #pragma unroll
                for (int j = 0; j < 8; j++) {
                    float s = 0.f;
                    #pragma unroll
                    for (int q = 0; q < 8; q++) s += u[q] * Ms[q * 8 + j];
                    v[r][j] = s;
                }
            }
        } else {
            #pragma unroll
            for (int p = 0; p < 8; p++)
                #pragma unroll
                for (int j = 0; j < 8; j++) v[p][j] = 0.f;
        }
        float* dst = &sm[(ch * 48 + pr * 8) * 256 + pc * 8];
        #pragma unroll
        for (int r = 0; r < 8; r++) {
            *(float4*)(dst + r * 256)     = make_float4(v[r][0], v[r][1], v[r][2], v[r][3]);
            *(float4*)(dst + r * 256 + 4) = make_float4(v[r][4], v[r][5], v[r][6], v[r][7]);
        }
    }
    __syncthreads();

    float wA[9], wB[9];
    #pragma unroll
    for (int t = 0; t < 9; t++) wA[t] = __ldg(&W_dw[c * 9 + t]);
    #pragma unroll
    for (int t = 0; t < 9; t++) wB[t] = __ldg(&W_dw[(c + HID) * 9 + t]);

    float* gdst = g_g + (size_t)(b * HID + c) * NPIX + (size_t)y0 * WW;
    for (int g4 = tid; g4 < 32 * 64; g4 += 384) {
        int r = g4 >> 6, w0 = (g4 & 63) * 4;
        float s1[4] = {0.f, 0.f, 0.f, 0.f};
        float s2[4] = {0.f, 0.f, 0.f, 0.f};
        #pragma unroll
        for (int dy = 0; dy < 3; dy++) {
            const float* rowA = &sm[(r + 7 + dy) * 256];
            const float* rowB = rowA + 48 * 256;
            float vA[6], vB[6];
            vA[0] = (w0 == 0)   ? 0.f : rowA[w0 - 1];
            vA[1] = rowA[w0];     vA[2] = rowA[w0 + 1];
            vA[3] = rowA[w0 + 2]; vA[4] = rowA[w0 + 3];
            vA[5] = (w0 == 252) ? 0.f : rowA[w0 + 4];
            vB[0] = (w0 == 0)   ? 0.f : rowB[w0 - 1];
            vB[1] = rowB[w0];     vB[2] = rowB[w0 + 1];
            vB[3] = rowB[w0 + 2]; vB[4] = rowB[w0 + 3];
            vB[5] = (w0 == 252) ? 0.f : rowB[w0 + 4];
            #pragma unroll
            for (int dx = 0; dx < 3; dx++) {
                float wa = wA[dy * 3 + dx], wb = wB[dy * 3 + dx];
                #pragma unroll
                for (int j = 0; j < 4; j++) {
                    s1[j] += wa * vA[j + dx];
                    s2[j] += wb * vB[j + dx];
                }
            }
        }
        float o[4];
        #pragma unroll
        for (int j = 0; j < 4; j++)
            o[j] = 0.5f * s1[j] * (1.f + erff(s1[j] * 0.70710678118654752f)) * s2[j];
        *(float4*)&gdst[r * 256 + w0] = make_float4(o[0], o[1], o[2], o[3]);
    }
}

// ---------------- K4: out = W_out @ g, 2-MMA split-A tf32 (R14 version) -----------
__global__ __launch_bounds__(256) void k_proj_out(float* __restrict__ out) {
    __shared__ unsigned Ah[64 * AS_STRIDE];
    __shared__ unsigned Al[64 * AS_STRIDE];
    __shared__ unsigned Bs[64 * BS_STRIDE];
    int n0 = blockIdx.x * 128;
    int b  = blockIdx.y;
    int tid = threadIdx.x;

    int warp = tid >> 5, lane = tid & 31;
    int wm = warp & 1, wn = warp >> 1;
    int g  = lane >> 2, tg = lane & 3;
    int mb = wm * 32, nb = wn * 32;

    float c[2][4][4];
    #pragma unroll
    for (int mi = 0; mi < 2; mi++)
        #pragma unroll
        for (int ni = 0; ni < 4; ni++)
            #pragma unroll
            for (int t = 0; t < 4; t++) c[mi][ni][t] = 0.f;

    for (int kk = 0; kk < 192; kk += 64) {
        for (int i = tid; i < 64 * 16; i += 256) {
            int k = i >> 4, m4 = (i & 15) * 4;
            float4 h = *(const float4*)(g_Wot_hi + (kk + k) * 64 + m4);
            float4 l = *(const float4*)(g_Wot_lo + (kk + k) * 64 + m4);
            unsigned* dh = &Ah[k * AS_STRIDE + m4];
            unsigned* dl = &Al[k * AS_STRIDE + m4];
            dh[0] = __float_as_uint(h.x); dh[1] = __float_as_uint(h.y);
            dh[2] = __float_as_uint(h.z); dh[3] = __float_as_uint(h.w);
            dl[0] = __float_as_uint(l.x); dl[1] = __float_as_uint(l.y);
            dl[2] = __float_as_uint(l.z); dl[3] = __float_as_uint(l.w);
        }
        for (int i = tid; i < 64 * 32; i += 256) {
            int k = i >> 5, n4 = (i & 31) * 4;
            float4 v = make_float4(0.f, 0.f, 0.f, 0.f);
            if (kk + k < HID)
                v = *(const float4*)(g_g + (size_t)(b * HID + kk + k) * NPIX + n0 + n4);
            unsigned* d = &Bs[k * BS_STRIDE + n4];
            d[0] = f2tf(v.x); d[1] = f2tf(v.y); d[2] = f2tf(v.z); d[3] = f2tf(v.w);
        }
        __syncthreads();

        #pragma unroll
        for (int ks = 0; ks < 8; ks++) {
            int k0 = ks * 8;
            unsigned ah[2][4], al[2][4];
            #pragma unroll
            for (int mi = 0; mi < 2; mi++) {
                int mloc = mb + mi * 16;
                ah[mi][0] = Ah[(k0 + tg)     * AS_STRIDE + mloc + g];
                ah[mi][1] = Ah[(k0 + tg)     * AS_STRIDE + mloc + g + 8];
                ah[mi][2] = Ah[(k0 + tg + 4) * AS_STRIDE + mloc + g];
                ah[mi][3] = Ah[(k0 + tg + 4) * AS_STRIDE + mloc + g + 8];
                al[mi][0] = Al[(k0 + tg)     * AS_STRIDE + mloc + g];
                al[mi][1] = Al[(k0 + tg)     * AS_STRIDE + mloc + g + 8];
                al[mi][2] = Al[(k0 + tg + 4) * AS_STRIDE + mloc + g];
                al[mi][3] = Al[(k0 + tg + 4) * AS_STRIDE + mloc + g + 8];
            }
            #pragma unroll
            for (int ni = 0; ni < 4; ni++) {
                int nloc = nb + ni * 8;
                unsigned b0 = Bs[(k0 + tg)     * BS_STRIDE + nloc + g];
                unsigned b1 = Bs[(k0 + tg + 4) * BS_STRIDE + nloc + g];
                #pragma unroll
                for (int mi = 0; mi < 2; mi++) {
                    MMA_TF32(c[mi][ni], al[mi][0], al[mi][1], al[mi][2], al[mi][3], b0, b1);
                    MMA_TF32(c[mi][ni], ah[mi][0], ah[mi][1], ah[mi][2], ah[mi][3], b0, b1);
                }
            }
        }
        __syncthreads();
    }

    float* outb = out + (size_t)b * 64 * NPIX + n0;
    #pragma unroll
    for (int mi = 0; mi < 2; mi++) {
        #pragma unroll
        for (int half = 0; half < 2; half++) {
            int cc = mb + mi * 16 + g + half * 8;      // 0..63, all valid
            float* orow = outb + (size_t)cc * NPIX;
            #pragma unroll
            for (int ni = 0; ni < 4; ni++) {
                int nloc = nb + ni * 8 + 2 * tg;
                float2 o;
                o.x = c[mi][ni][half * 2];
                o.y = c[mi][ni][half * 2 + 1];
                *(float2*)(orow + nloc) = o;
            }
        }
    }
}

// ---------------- launch ----------------
extern "C" void kernel_launch(void* const* d_in, const int* in_sizes, int n_in,
                              void* d_out, int out_size) {
    (void)in_sizes; (void)n_in; (void)out_size;
    const float* x     = (const float*)d_in[0];
    const float* W_in  = (const float*)d_in[1];
    const float* W_dw  = (const float*)d_in[2];
    const float* quant = (const float*)d_in[3];
    const float* W_out = (const float*)d_in[4];
    float* out = (float*)d_out;

    cudaFuncSetAttribute(k_fuse, cudaFuncAttributeMaxDynamicSharedMemorySize,
                         96 * 256 * 4);

    k_transpose<<<85, 256>>>(W_in, W_out);
    k_dct<<<dim3(4, 64, 4), 256>>>(x);
    k_proj_in<<<dim3(6, 512, 4), 256>>>(quant);
    k_fuse<<<dim3(8, 170, 4), 384, 96 * 256 * 4>>>(W_dw);
    k_proj_out<<<dim3(512, 4), 256>>>(out);
}

// round 16
// speedup vs baseline: 1.8102x; 1.0841x over previous
#include <cuda_runtime.h>
#include <math.h>

#define BB   4
#define CIN  64
#define C2   340
#define HID  170
#define HH   256
#define WW   256
#define NPIX 65536   /* 256*256 */

// ---------------- scratch (device globals; no allocations) ----------------
__device__ float g_xd[BB * CIN * NPIX];          // DCT(x): 67 MB
__device__ float g_yq[BB * C2  * NPIX];          // quant * (W_in @ DCT(x)): 356 MB
__device__ float g_g [BB * HID * NPIX];          // gelu(x1)*x2: 178 MB
__device__ float g_Wt [64  * 384];               // W_in^T  [k][m], stride 384 (zero padded BSS)
__device__ float g_Wot_hi[192 * 64];             // W_out^T hi, K padded 170->192
__device__ float g_Wot_lo[192 * 64];             // W_out^T lo

__device__ __forceinline__ unsigned f2tf(float f) {
    unsigned u;
    asm("cvt.rna.tf32.f32 %0, %1;" : "=r"(u) : "f"(f));
    return u;
}

#define MMA_TF32(C, A0, A1, A2, A3, B0, B1)                                  \
    asm("mma.sync.aligned.m16n8k8.row.col.f32.tf32.tf32.f32 "                \
        "{%0,%1,%2,%3}, {%4,%5,%6,%7}, {%8,%9}, {%0,%1,%2,%3};"              \
        : "+f"(C[0]), "+f"(C[1]), "+f"(C[2]), "+f"(C[3])                     \
        : "r"(A0), "r"(A1), "r"(A2), "r"(A3), "r"(B0), "r"(B1))

// ---------------- weight transpose; W_out also gets offline tf32 hi/lo split ----
__global__ void k_transpose(const float* __restrict__ W_in,
                            const float* __restrict__ W_out) {
    int t = blockIdx.x * blockDim.x + threadIdx.x;
    if (t < C2 * CIN) {               // W_in [340][64] -> g_Wt [64][384]
        int m = t / CIN, k = t % CIN;
        g_Wt[k * 384 + m] = W_in[t];
    }
    if (t < 64 * HID) {               // W_out [64][170] -> [170][64] hi/lo
        int m = t / HID, k = t % HID;
        float w  = W_out[t];
        float hi = __uint_as_float(f2tf(w));
        g_Wot_hi[k * 64 + m] = hi;
        g_Wot_lo[k * 64 + m] = __uint_as_float(f2tf(w - hi));
    }
    if (t < 22 * 64) {                // zero pad rows 170..191
        g_Wot_hi[170 * 64 + t] = 0.f;
        g_Wot_lo[170 * 64 + t] = 0.f;
    }
}

// ---------------- K1: per-patch 2D DCT, register-resident (R10, measured) ----------
__global__ __launch_bounds__(256) void k_dct(const float* __restrict__ x) {
    __shared__ float Ms[64];
    int tid = threadIdx.x;
    if (tid < 64) {
        int i = tid >> 3, j = tid & 7;
        Ms[tid] = (i == 0) ? 0.35355339059327373f
                           : 0.5f * cospif((float)(i * (2 * j + 1)) * (1.0f / 16.0f));
    }
    __syncthreads();
    int pr = blockIdx.x * 8 + (tid >> 5);
    int pc = tid & 31;
    int c = blockIdx.y, b = blockIdx.z;
    const float* src = x + ((size_t)(b * CIN + c) * HH + pr * 8) * WW + pc * 8;
    float v[8][8];
    #pragma unroll
    for (int p = 0; p < 8; p++) {
        float4 a = *(const float4*)(src + (size_t)p * WW);
        float4 d = *(const float4*)(src + (size_t)p * WW + 4);
        v[p][0] = a.x; v[p][1] = a.y; v[p][2] = a.z; v[p][3] = a.w;
        v[p][4] = d.x; v[p][5] = d.y; v[p][6] = d.z; v[p][7] = d.w;
    }
    #pragma unroll
    for (int j = 0; j < 8; j++) {
        float u[8];
        #pragma unroll
        for (int p = 0; p < 8; p++) u[p] = v[p][j];
        #pragma unroll
        for (int i = 0; i < 8; i++) {
            float s = 0.f;
            #pragma unroll
            for (int p = 0; p < 8; p++) s += Ms[i * 8 + p] * u[p];
            v[i][j] = s;
        }
    }
    float* dst = g_xd + ((size_t)(b * CIN + c) * HH + pr * 8) * WW + pc * 8;
    #pragma unroll
    for (int i = 0; i < 8; i++) {
        float u[8];
        #pragma unroll
        for (int q = 0; q < 8; q++) u[q] = v[i][q];
        float y[8];
        #pragma unroll
        for (int j = 0; j < 8; j++) {
            float s = 0.f;
            #pragma unroll
            for (int q = 0; q < 8; q++) s += u[q] * Ms[j * 8 + q];
            y[j] = s;
        }
        *(float4*)(dst + (size_t)i * WW)     = make_float4(y[0], y[1], y[2], y[3]);
        *(float4*)(dst + (size_t)i * WW + 4) = make_float4(y[4], y[5], y[6], y[7]);
    }
}

// ---------------- K2: yq = quant * (W_in @ xd), 1-MMA tf32 (R11, measured) --------
#define AS_STRIDE 68
#define BS_STRIDE 132
__global__ __launch_bounds__(256) void k_proj_in(const float* __restrict__ quant) {
    __shared__ unsigned As[64 * AS_STRIDE];   // [k][m], tf32, padded
    __shared__ unsigned Bs[64 * BS_STRIDE];   // [k][n], tf32, padded
    int m0 = blockIdx.x * 64;
    int n0 = blockIdx.y * 128;
    int b  = blockIdx.z;
    int tid = threadIdx.x;

    for (int i = tid; i < 64 * 16; i += 256) {            // A tile
        int k = i >> 4, m4 = (i & 15) * 4;
        float4 w = *(const float4*)(g_Wt + k * 384 + m0 + m4);
        unsigned* d = &As[k * AS_STRIDE + m4];
        d[0] = f2tf(w.x); d[1] = f2tf(w.y); d[2] = f2tf(w.z); d[3] = f2tf(w.w);
    }
    const float* Bbase = g_xd + (size_t)b * CIN * NPIX + n0;
    for (int i = tid; i < 64 * 32; i += 256) {            // B tile
        int k = i >> 5, n4 = (i & 31) * 4;
        float4 w = *(const float4*)(Bbase + (size_t)k * NPIX + n4);
        unsigned* d = &Bs[k * BS_STRIDE + n4];
        d[0] = f2tf(w.x); d[1] = f2tf(w.y); d[2] = f2tf(w.z); d[3] = f2tf(w.w);
    }
    __syncthreads();

    int warp = tid >> 5, lane = tid & 31;
    int wm = warp & 1, wn = warp >> 1;                    // 2 x 4 warp grid
    int g  = lane >> 2, tg = lane & 3;
    int mb = wm * 32, nb = wn * 32;

    float c[2][4][4];
    #pragma unroll
    for (int mi = 0; mi < 2; mi++)
        #pragma unroll
        for (int ni = 0; ni < 4; ni++)
            #pragma unroll
            for (int t = 0; t < 4; t++) c[mi][ni][t] = 0.f;

    #pragma unroll
    for (int ks = 0; ks < 8; ks++) {
        int k0 = ks * 8;
        unsigned a[2][4];
        #pragma unroll
        for (int mi = 0; mi < 2; mi++) {
            int mloc = mb + mi * 16;
            a[mi][0] = As[(k0 + tg)     * AS_STRIDE + mloc + g];
            a[mi][1] = As[(k0 + tg)     * AS_STRIDE + mloc + g + 8];
            a[mi][2] = As[(k0 + tg + 4) * AS_STRIDE + mloc + g];
            a[mi][3] = As[(k0 + tg + 4) * AS_STRIDE + mloc + g + 8];
        }
        #pragma unroll
        for (int ni = 0; ni < 4; ni++) {
            int nloc = nb + ni * 8;
            unsigned b0 = Bs[(k0 + tg)     * BS_STRIDE + nloc + g];
            unsigned b1 = Bs[(k0 + tg + 4) * BS_STRIDE + nloc + g];
            #pragma unroll
            for (int mi = 0; mi < 2; mi++) {
                MMA_TF32(c[mi][ni], a[mi][0], a[mi][1], a[mi][2], a[mi][3], b0, b1);
            }
        }
    }

    int fi = (n0 >> 8) & 7;
    float* outb = g_yq + (size_t)b * C2 * NPIX + n0;
    #pragma unroll
    for (int mi = 0; mi < 2; mi++) {
        #pragma unroll
        for (int half = 0; half < 2; half++) {
            int cc = m0 + mb + mi * 16 + g + half * 8;
            if (cc < C2) {
                const float* qrow = quant + cc * 64 + fi * 8;
                float* orow = outb + (size_t)cc * NPIX;
                #pragma unroll
                for (int ni = 0; ni < 4; ni++) {
                    int nloc = nb + ni * 8 + 2 * tg;
                    int fj = 2 * tg;
                    float2 o;
                    o.x = c[mi][ni][half * 2]     * qrow[fj];
                    o.y = c[mi][ni][half * 2 + 1] * qrow[fj + 1];
                    *(float2*)(orow + nloc) = o;
                }
            }
        }
    }
}

// ---------------- K3: fused IDCT + depthwise 3x3 + GLU(gelu) -> g ----------------
// R10 body; SINGLE change this round: __launch_bounds__(384, 2) to co-resident
// 2 CTAs/SM (needs regs <= 85; was 94 -> 1 CTA, occ 17.8%). smem 2x96KB fits 227KB.
__global__ __launch_bounds__(384, 2) void k_fuse(const float* __restrict__ W_dw) {
    extern __shared__ float sm[];                  // 96 rows * 256 floats = 96 KB
    __shared__ float Ms[64];
    int tid = threadIdx.x;
    if (tid < 64) {
        int i = tid >> 3, j = tid & 7;
        Ms[tid] = (i == 0) ? 0.35355339059327373f
                           : 0.5f * cospif((float)(i * (2 * j + 1)) * (1.0f / 16.0f));
    }
    __syncthreads();

    int yt = blockIdx.x, c = blockIdx.y, b = blockIdx.z;
    int y0 = yt * 32;

    {
        int ch  = tid / 192;
        int rem = tid - ch * 192;
        int pr  = rem >> 5;
        int pc  = rem & 31;
        const float* src = g_yq + (size_t)(b * C2 + c + ch * HID) * NPIX;
        int gy0 = y0 - 8 + pr * 8;
        float v[8][8];
        if (gy0 >= 0 && gy0 < HH) {
            #pragma unroll
            for (int p = 0; p < 8; p++) {
                const float* row = src + (size_t)(gy0 + p) * WW + pc * 8;
                float4 a = *(const float4*)row;
                float4 d = *(const float4*)(row + 4);
                v[p][0] = a.x; v[p][1] = a.y; v[p][2] = a.z; v[p][3] = a.w;
                v[p][4] = d.x; v[p][5] = d.y; v[p][6] = d.z; v[p][7] = d.w;
            }
            #pragma unroll
            for (int j = 0; j < 8; j++) {
                float u[8];
                #pragma unroll
                for (int p = 0; p < 8; p++) u[p] = v[p][j];
                #pragma unroll
                for (int r = 0; r < 8; r++) {
                    float s = 0.f;
                    #pragma unroll
                    for (int p = 0; p < 8; p++) s += Ms[p * 8 + r] * u[p];
                    v[r][j] = s;
                }
            }
            #pragma unroll
            for (int r = 0; r < 8; r++) {
                float u[8];
                #pragma unroll
                for (int q = 0; q < 8; q++) u[q] = v[r][q];
                #pragma unroll
                for (int j = 0; j < 8; j++) {
                    float s = 0.f;
                    #pragma unroll
                    for (int q = 0; q < 8; q++) s += u[q] * Ms[q * 8 + j];
                    v[r][j] = s;
                }
            }
        } else {
            #pragma unroll
            for (int p = 0; p < 8; p++)
                #pragma unroll
                for (int j = 0; j < 8; j++) v[p][j] = 0.f;
        }
        float* dst = &sm[(ch * 48 + pr * 8) * 256 + pc * 8];
        #pragma unroll
        for (int r = 0; r < 8; r++) {
            *(float4*)(dst + r * 256)     = make_float4(v[r][0], v[r][1], v[r][2], v[r][3]);
            *(float4*)(dst + r * 256 + 4) = make_float4(v[r][4], v[r][5], v[r][6], v[r][7]);
        }
    }
    __syncthreads();

    float wA[9], wB[9];
    #pragma unroll
    for (int t = 0; t < 9; t++) wA[t] = __ldg(&W_dw[c * 9 + t]);
    #pragma unroll
    for (int t = 0; t < 9; t++) wB[t] = __ldg(&W_dw[(c + HID) * 9 + t]);

    float* gdst = g_g + (size_t)(b * HID + c) * NPIX + (size_t)y0 * WW;
    for (int g4 = tid; g4 < 32 * 64; g4 += 384) {
        int r = g4 >> 6, w0 = (g4 & 63) * 4;
        float s1[4] = {0.f, 0.f, 0.f, 0.f};
        float s2[4] = {0.f, 0.f, 0.f, 0.f};
        #pragma unroll
        for (int dy = 0; dy < 3; dy++) {
            const float* rowA = &sm[(r + 7 + dy) * 256];
            const float* rowB = rowA + 48 * 256;
            float vA[6], vB[6];
            vA[0] = (w0 == 0)   ? 0.f : rowA[w0 - 1];
            vA[1] = rowA[w0];     vA[2] = rowA[w0 + 1];
            vA[3] = rowA[w0 + 2]; vA[4] = rowA[w0 + 3];
            vA[5] = (w0 == 252) ? 0.f : rowA[w0 + 4];
            vB[0] = (w0 == 0)   ? 0.f : rowB[w0 - 1];
            vB[1] = rowB[w0];     vB[2] = rowB[w0 + 1];
            vB[3] = rowB[w0 + 2]; vB[4] = rowB[w0 + 3];
            vB[5] = (w0 == 252) ? 0.f : rowB[w0 + 4];
            #pragma unroll
            for (int dx = 0; dx < 3; dx++) {
                float wa = wA[dy * 3 + dx], wb = wB[dy * 3 + dx];
                #pragma unroll
                for (int j = 0; j < 4; j++) {
                    s1[j] += wa * vA[j + dx];
                    s2[j] += wb * vB[j + dx];
                }
            }
        }
        float o[4];
        #pragma unroll
        for (int j = 0; j < 4; j++)
            o[j] = 0.5f * s1[j] * (1.f + erff(s1[j] * 0.70710678118654752f)) * s2[j];
        *(float4*)&gdst[r * 256 + w0] = make_float4(o[0], o[1], o[2], o[3]);
    }
}

// ---------------- K4: out = W_out @ g, 2-MMA split-A tf32 (R14, measured) ---------
__global__ __launch_bounds__(256) void k_proj_out(float* __restrict__ out) {
    __shared__ unsigned Ah[64 * AS_STRIDE];
    __shared__ unsigned Al[64 * AS_STRIDE];
    __shared__ unsigned Bs[64 * BS_STRIDE];
    int n0 = blockIdx.x * 128;
    int b  = blockIdx.y;
    int tid = threadIdx.x;

    int warp = tid >> 5, lane = tid & 31;
    int wm = warp & 1, wn = warp >> 1;
    int g  = lane >> 2, tg = lane & 3;
    int mb = wm * 32, nb = wn * 32;

    float c[2][4][4];
    #pragma unroll
    for (int mi = 0; mi < 2; mi++)
        #pragma unroll
        for (int ni = 0; ni < 4; ni++)
            #pragma unroll
            for (int t = 0; t < 4; t++) c[mi][ni][t] = 0.f;

    for (int kk = 0; kk < 192; kk += 64) {
        for (int i = tid; i < 64 * 16; i += 256) {
            int k = i >> 4, m4 = (i & 15) * 4;
            float4 h = *(const float4*)(g_Wot_hi + (kk + k) * 64 + m4);
            float4 l = *(const float4*)(g_Wot_lo + (kk + k) * 64 + m4);
            unsigned* dh = &Ah[k * AS_STRIDE + m4];
            unsigned* dl = &Al[k * AS_STRIDE + m4];
            dh[0] = __float_as_uint(h.x); dh[1] = __float_as_uint(h.y);
            dh[2] = __float_as_uint(h.z); dh[3] = __float_as_uint(h.w);
            dl[0] = __float_as_uint(l.x); dl[1] = __float_as_uint(l.y);
            dl[2] = __float_as_uint(l.z); dl[3] = __float_as_uint(l.w);
        }
        for (int i = tid; i < 64 * 32; i += 256) {
            int k = i >> 5, n4 = (i & 31) * 4;
            float4 v = make_float4(0.f, 0.f, 0.f, 0.f);
            if (kk + k < HID)
                v = *(const float4*)(g_g + (size_t)(b * HID + kk + k) * NPIX + n0 + n4);
            unsigned* d = &Bs[k * BS_STRIDE + n4];
            d[0] = f2tf(v.x); d[1] = f2tf(v.y); d[2] = f2tf(v.z); d[3] = f2tf(v.w);
        }
        __syncthreads();

        #pragma unroll
        for (int ks = 0; ks < 8; ks++) {
            int k0 = ks * 8;
            unsigned ah[2][4], al[2][4];
            #pragma unroll
            for (int mi = 0; mi < 2; mi++) {
                int mloc = mb + mi * 16;
                ah[mi][0] = Ah[(k0 + tg)     * AS_STRIDE + mloc + g];
                ah[mi][1] = Ah[(k0 + tg)     * AS_STRIDE + mloc + g + 8];
                ah[mi][2] = Ah[(k0 + tg + 4) * AS_STRIDE + mloc + g];
                ah[mi][3] = Ah[(k0 + tg + 4) * AS_STRIDE + mloc + g + 8];
                al[mi][0] = Al[(k0 + tg)     * AS_STRIDE + mloc + g];
                al[mi][1] = Al[(k0 + tg)     * AS_STRIDE + mloc + g + 8];
                al[mi][2] = Al[(k0 + tg + 4) * AS_STRIDE + mloc + g];
                al[mi][3] = Al[(k0 + tg + 4) * AS_STRIDE + mloc + g + 8];
            }
            #pragma unroll
            for (int ni = 0; ni < 4; ni++) {
                int nloc = nb + ni * 8;
                unsigned b0 = Bs[(k0 + tg)     * BS_STRIDE + nloc + g];
                unsigned b1 = Bs[(k0 + tg + 4) * BS_STRIDE + nloc + g];
                #pragma unroll
                for (int mi = 0; mi < 2; mi++) {
                    MMA_TF32(c[mi][ni], al[mi][0], al[mi][1], al[mi][2], al[mi][3], b0, b1);
                    MMA_TF32(c[mi][ni], ah[mi][0], ah[mi][1], ah[mi][2], ah[mi][3], b0, b1);
                }
            }
        }
        __syncthreads();
    }

    float* outb = out + (size_t)b * 64 * NPIX + n0;
    #pragma unroll
    for (int mi = 0; mi < 2; mi++) {
        #pragma unroll
        for (int half = 0; half < 2; half++) {
            int cc = mb + mi * 16 + g + half * 8;      // 0..63, all valid
            float* orow = outb + (size_t)cc * NPIX;
            #pragma unroll
            for (int ni = 0; ni < 4; ni++) {
                int nloc = nb + ni * 8 + 2 * tg;
                float2 o;
                o.x = c[mi][ni][half * 2];
                o.y = c[mi][ni][half * 2 + 1];
                *(float2*)(orow + nloc) = o;
            }
        }
    }
}

// ---------------- launch ----------------
extern "C" void kernel_launch(void* const* d_in, const int* in_sizes, int n_in,
                              void* d_out, int out_size) {
    (void)in_sizes; (void)n_in; (void)out_size;
    const float* x     = (const float*)d_in[0];
    const float* W_in  = (const float*)d_in[1];
    const float* W_dw  = (const float*)d_in[2];
    const float* quant = (const float*)d_in[3];
    const float* W_out = (const float*)d_in[4];
    float* out = (float*)d_out;

    cudaFuncSetAttribute(k_fuse, cudaFuncAttributeMaxDynamicSharedMemorySize,
                         96 * 256 * 4);

    k_transpose<<<85, 256>>>(W_in, W_out);
    k_dct<<<dim3(4, 64, 4), 256>>>(x);
    k_proj_in<<<dim3(6, 512, 4), 256>>>(quant);
    k_fuse<<<dim3(8, 170, 4), 384, 96 * 256 * 4>>>(W_dw);
    k_proj_out<<<dim3(512, 4), 256>>>(out);
}